// round 16
// baseline (speedup 1.0000x reference)
#include <cuda_runtime.h>
#include <cuda_fp16.h>
#include <cstdint>
#include <math.h>

#define B_  4
#define S_  2048
#define E_  1024
#define H_  16
#define D_  64
#define T_  (B_*S_)     // 8192 tokens
#define HD_ (H_*D_)     // 1024

// softmax scale folded into q at QKV epilogue: 1/sqrt(64) * log2(e)
#define QSCALE (0.125f * 1.4426950408889634f)

// ---------------------------------------------------------------------------
// Scratch (static device arrays; no runtime allocation)
// ---------------------------------------------------------------------------
__device__ __half g_x[(size_t)T_*E_];          // fp16 x [T,E]
__device__ __half g_qkv[(size_t)3*T_*HD_];     // q|k|v, each [B,H,S,D] (q pre-scaled)
__device__ __half g_o[(size_t)T_*HD_];         // ctx [B,S,H,D] == [T, HD]
__device__ __half g_wqkvt[(size_t)3*HD_*E_];   // K-major [n][e], q|k|v
__device__ __half g_wpt[(size_t)E_*HD_];       // K-major [n=e][c]

// ---------------------------------------------------------------------------
// PTX helpers (plain sm_103-target-safe: mma.sync + ldmatrix + cp.async)
// ---------------------------------------------------------------------------
__device__ __forceinline__ uint32_t smem_u32(const void* p) {
    return (uint32_t)__cvta_generic_to_shared(p);
}
__device__ __forceinline__ void cp_async16(uint32_t dst, const void* src) {
    asm volatile("cp.async.cg.shared.global [%0], [%1], 16;\n" :: "r"(dst), "l"(src));
}
__device__ __forceinline__ void cp_commit() {
    asm volatile("cp.async.commit_group;\n" ::: "memory");
}
template<int N> __device__ __forceinline__ void cp_wait() {
    asm volatile("cp.async.wait_group %0;\n" :: "n"(N) : "memory");
}
__device__ __forceinline__ void mma_f16(float* c,
    uint32_t a0, uint32_t a1, uint32_t a2, uint32_t a3,
    uint32_t b0, uint32_t b1)
{
    asm volatile(
        "mma.sync.aligned.m16n8k16.row.col.f32.f16.f16.f32 "
        "{%0,%1,%2,%3},{%4,%5,%6,%7},{%8,%9},{%0,%1,%2,%3};"
        : "+f"(c[0]), "+f"(c[1]), "+f"(c[2]), "+f"(c[3])
        : "r"(a0), "r"(a1), "r"(a2), "r"(a3), "r"(b0), "r"(b1));
}
__device__ __forceinline__ void ldsm_x4(uint32_t* r, uint32_t a) {
    asm volatile("ldmatrix.sync.aligned.m8n8.x4.shared.b16 {%0,%1,%2,%3}, [%4];"
        : "=r"(r[0]), "=r"(r[1]), "=r"(r[2]), "=r"(r[3]) : "r"(a));
}
__device__ __forceinline__ void ldsm_x4t(uint32_t* r, uint32_t a) {
    asm volatile("ldmatrix.sync.aligned.m8n8.x4.trans.shared.b16 {%0,%1,%2,%3}, [%4];"
        : "=r"(r[0]), "=r"(r[1]), "=r"(r[2]), "=r"(r[3]) : "r"(a));
}

// ---------------------------------------------------------------------------
// Fused pre-pass: one launch, three sections by blockIdx.x
// ---------------------------------------------------------------------------
__global__ __launch_bounds__(256) void prep_kernel(
    const float* __restrict__ x,
    const float* __restrict__ Wq,
    const float* __restrict__ Wk,
    const float* __restrict__ Wv,
    const float* __restrict__ Wp,
    __half* __restrict__ xd,
    __half* __restrict__ wqkvt,
    __half* __restrict__ wpt)
{
    __shared__ float tile[32][33];
    int bid = blockIdx.x;
    int tid = threadIdx.x;

    if (bid < 4096) {
        int i = (bid * 256 + tid) * 8;
        float4 v0 = *(const float4*)(x + i);
        float4 v1 = *(const float4*)(x + i + 4);
        __half2 h0 = __floats2half2_rn(v0.x, v0.y);
        __half2 h1 = __floats2half2_rn(v0.z, v0.w);
        __half2 h2 = __floats2half2_rn(v1.x, v1.y);
        __half2 h3 = __floats2half2_rn(v1.z, v1.w);
        uint4 st;
        st.x = *(uint32_t*)&h0; st.y = *(uint32_t*)&h1;
        st.z = *(uint32_t*)&h2; st.w = *(uint32_t*)&h3;
        *(uint4*)(xd + i) = st;
        return;
    }

    int tx = tid & 31, ty = tid >> 5;

    if (bid < 7168) {
        int idx = bid - 4096;
        int z = idx >> 6;
        int r0 = ((idx >> 1) & 31) * 32;
        int c0 = (idx & 1) * 32;
        const float* W = (z < 16) ? Wq : (z < 32) ? Wk : Wv;
        const float* s = W + (size_t)(z & 15) * E_ * D_;
        __half* d = wqkvt + (size_t)z * D_ * E_;
        #pragma unroll
        for (int i = ty; i < 32; i += 8)
            tile[i][tx] = s[(size_t)(r0 + i) * D_ + c0 + tx];
        __syncthreads();
        #pragma unroll
        for (int i = ty; i < 32; i += 8)
            d[(size_t)(c0 + i) * E_ + r0 + tx] = __float2half(tile[tx][i]);
        return;
    }

    {
        int idx = bid - 7168;
        int c0 = (idx & 31) * 32;
        int r0 = (idx >> 5) * 32;
        #pragma unroll
        for (int i = ty; i < 32; i += 8)
            tile[i][tx] = Wp[(size_t)(r0 + i) * E_ + c0 + tx];
        __syncthreads();
        #pragma unroll
        for (int i = ty; i < 32; i += 8)
            wpt[(size_t)(c0 + i) * HD_ + r0 + tx] = __float2half(tile[tx][i]);
    }
}

// ---------------------------------------------------------------------------
// fp16 mma.sync GEMM: CTA 128x256, BK=64, 3 stages, 512 threads,
// 16 warps (4m x 4n), warp tile 32x64, 1 CTA/SM (full RF, 16 warps/SM).
// Halves smem traffic per flop vs 128x128 (A tile amortized over 2x N).
// MODE 0: fused QKV -> g_qkv; q section scaled by QSCALE.  MODE 1: [T,E] fp32.
// ---------------------------------------------------------------------------
#define GEMM_BK     64
#define GEMM_STAGES 3
#define GEMM_KT     (E_ / GEMM_BK)           // 16
#define GEMM_STR    72                       // halfs per smem row (64+8 pad)
#define GEMM_AROWS  128
#define GEMM_BROWS  256
#define GEMM_ATILEH (GEMM_AROWS * GEMM_STR)
#define GEMM_STAGEH ((GEMM_AROWS + GEMM_BROWS) * GEMM_STR)
#define GEMM_SMEM   (GEMM_STAGES * GEMM_STAGEH * 2)    // 165888 B

__device__ __forceinline__ void gemm_load_stage(
    const __half* __restrict__ Ag, const __half* __restrict__ Bg,
    uint32_t abase, uint32_t bbase, int tid)
{
    // A: 128 rows x 8 chunks = 1024; B: 256 rows x 8 chunks = 2048; total 3072
    // 512 threads -> 6 iterations
    #pragma unroll
    for (int j = 0; j < 6; j++) {
        int p = tid + j * 512;
        if (p < 1024) {
            int r = p >> 3, ch = p & 7;
            cp_async16(abase + (uint32_t)(r * (GEMM_STR * 2) + ch * 16),
                       Ag + (size_t)r * E_ + ch * 8);
        } else {
            int q = p - 1024;
            int r = q >> 3, ch = q & 7;
            cp_async16(bbase + (uint32_t)(r * (GEMM_STR * 2) + ch * 16),
                       Bg + (size_t)r * E_ + ch * 8);
        }
    }
}

template<int MODE>
__global__ __launch_bounds__(512, 1) void gemm_mma(
    const __half* __restrict__ A,
    const __half* __restrict__ Bw,
    const float* __restrict__ b0p,
    const float* __restrict__ b1p,
    const float* __restrict__ b2p,
    void* __restrict__ outp)
{
    extern __shared__ __align__(16) __half smem[];
    uint32_t sb = smem_u32(smem);

    int tid = threadIdx.x;
    int wid = tid >> 5, lane = tid & 31;
    int g = lane >> 2, c = lane & 3;
    int lr = lane & 15, lc = lane >> 4;
    int wm = wid & 3, wn = wid >> 2;          // 4m x 4n warp grid
    int m0 = blockIdx.x * 128;
    int n0 = blockIdx.y * 256;

    const __half* Abase = A + (size_t)m0 * E_;
    const __half* Bbase = Bw + (size_t)n0 * E_;

    float cfr[2][8][4];
    #pragma unroll
    for (int mf = 0; mf < 2; mf++)
        #pragma unroll
        for (int nf = 0; nf < 8; nf++)
            #pragma unroll
            for (int i = 0; i < 4; i++) cfr[mf][nf][i] = 0.f;

    #pragma unroll
    for (int s = 0; s < GEMM_STAGES - 1; s++) {
        gemm_load_stage(Abase + s * GEMM_BK, Bbase + s * GEMM_BK,
                        sb + s * GEMM_STAGEH * 2,
                        sb + (s * GEMM_STAGEH + GEMM_ATILEH) * 2, tid);
        cp_commit();
    }

    for (int kt = 0; kt < GEMM_KT; kt++) {
        cp_wait<GEMM_STAGES - 2>();
        __syncthreads();

        int ktn = kt + GEMM_STAGES - 1;
        if (ktn < GEMM_KT) {
            int sn = ktn % GEMM_STAGES;
            gemm_load_stage(Abase + ktn * GEMM_BK, Bbase + ktn * GEMM_BK,
                            sb + sn * GEMM_STAGEH * 2,
                            sb + (sn * GEMM_STAGEH + GEMM_ATILEH) * 2, tid);
        }
        cp_commit();

        int s = kt % GEMM_STAGES;
        uint32_t As_u = sb + s * GEMM_STAGEH * 2;
        uint32_t Bs_u = As_u + GEMM_ATILEH * 2;

        #pragma unroll
        for (int kc = 0; kc < 4; kc++) {
            int k0 = kc * 16 + 8 * lc;
            uint32_t afr[2][4];
            #pragma unroll
            for (int mf = 0; mf < 2; mf++)
                ldsm_x4(afr[mf],
                    As_u + (uint32_t)((wm * 32 + mf * 16 + lr) * GEMM_STR + k0) * 2);
            #pragma unroll
            for (int np = 0; np < 4; np++) {
                uint32_t bfr[4];
                ldsm_x4(bfr,
                    Bs_u + (uint32_t)((wn * 64 + np * 16 + lr) * GEMM_STR + k0) * 2);
                mma_f16(cfr[0][2*np+0], afr[0][0], afr[0][1], afr[0][2], afr[0][3], bfr[0], bfr[2]);
                mma_f16(cfr[1][2*np+0], afr[1][0], afr[1][1], afr[1][2], afr[1][3], bfr[0], bfr[2]);
                mma_f16(cfr[0][2*np+1], afr[0][0], afr[0][1], afr[0][2], afr[0][3], bfr[1], bfr[3]);
                mma_f16(cfr[1][2*np+1], afr[1][0], afr[1][1], afr[1][2], afr[1][3], bfr[1], bfr[3]);
            }
        }
    }

    #pragma unroll
    for (int mf = 0; mf < 2; mf++) {
        #pragma unroll
        for (int half_ = 0; half_ < 2; half_++) {
            int row = wm * 32 + mf * 16 + g + half_ * 8;
            int t = m0 + row;
            #pragma unroll
            for (int nf = 0; nf < 8; nf++) {
                int col = n0 + wn * 64 + nf * 8 + 2 * c;
                const float* bp_ = (col < 1024) ? b0p : (col < 2048) ? b1p : b2p;
                int cb = col & 1023;
                float vx = cfr[mf][nf][2 * half_ + 0] + bp_[cb];
                float vy = cfr[mf][nf][2 * half_ + 1] + bp_[cb + 1];
                if (MODE == 0) {
                    if (col < 1024) { vx *= QSCALE; vy *= QSCALE; }
                    __half* ob = (__half*)outp + (size_t)(col >> 10) * ((size_t)T_ * HD_);
                    int b = t >> 11, s_ = t & 2047;
                    int h = cb >> 6, d0 = cb & 63;
                    __half2 hv = __floats2half2_rn(vx, vy);
                    *(__half2*)(ob + (((size_t)(b * H_ + h)) * S_ + s_) * D_ + d0) = hv;
                } else {
                    float2 v; v.x = vx; v.y = vy;
                    *(float2*)((float*)outp + (size_t)t * E_ + col) = v;
                }
            }
        }
    }
}

// ---------------------------------------------------------------------------
// Flash attention (round-15 config): 128 threads / 4 warps, m32 x n64,
// BQ=128, balanced q-tile pairs, 3-stage KV ring, one barrier per tile.
// ---------------------------------------------------------------------------
#define AT_STR 72          // halfs per smem row (64 + 8 pad)
#define ATTN_SMEM ((128 + 3*64 + 3*64) * AT_STR * 2)   // 73728 B
#define NQT (S_ / 128)     // 16 q-tiles

__global__ __launch_bounds__(128, 2) void attn_kernel(
    const __half* __restrict__ q,
    const __half* __restrict__ k,
    const __half* __restrict__ v,
    __half* __restrict__ o)
{
    extern __shared__ __align__(16) __half smh[];
    __half* Qs = smh;                        // [128][72]
    __half* Ks = Qs + 128 * AT_STR;          // [3][64][72]
    __half* Vs = Ks + 3 * 64 * AT_STR;       // [3][64][72]

    uint32_t Qs_u = smem_u32(Qs);
    uint32_t Ks_u = smem_u32(Ks);
    uint32_t Vs_u = smem_u32(Vs);

    int tid = threadIdx.x;
    int lane = tid & 31, wid = tid >> 5;
    int g = lane >> 2, c = lane & 3;
    int lr = lane & 15, lc = lane >> 4;
    int bx = blockIdx.x;                     // 0..7
    int bh = blockIdx.y;

    const __half* qb = q + (size_t)bh * S_ * D_;
    const __half* kb = k + (size_t)bh * S_ * D_;
    const __half* vb = v + (size_t)bh * S_ * D_;
    int b = bh >> 4, h = bh & 15;

    #pragma unroll 1
    for (int pass = 0; pass < 2; pass++) {
        int qt = pass ? bx : (NQT - 1 - bx);
        int q0 = qt * 128;

        __syncthreads();   // fence pass-0 laggards

        #pragma unroll
        for (int it = 0; it < 8; it++) {
            int p = tid + it * 128;
            int r = p >> 3, ch = p & 7;
            cp_async16(Qs_u + (uint32_t)(r * AT_STR + ch * 8) * 2,
                       qb + (size_t)(q0 + r) * D_ + ch * 8);
        }
        #pragma unroll
        for (int it = 0; it < 8; it++) {
            int p = tid + it * 128;
            int sel = p >> 9;
            int pp = p & 511;
            int r = pp >> 3, ch = pp & 7;
            uint32_t dst = (sel ? Vs_u : Ks_u) + (uint32_t)(r * AT_STR + ch * 8) * 2;
            const __half* src = (sel ? vb : kb) + (size_t)r * D_ + ch * 8;
            cp_async16(dst, src);
        }
        cp_commit();

        #pragma unroll
        for (int l = 0; l < 8; l++) {
            int p = tid + l * 128;
            int sel = p >> 9;
            int pp = p & 511;
            int r = pp >> 3, ch = pp & 7;
            uint32_t dst = (sel ? Vs_u : Ks_u)
                         + (uint32_t)(64 * AT_STR + r * AT_STR + ch * 8) * 2;
            const __half* src = (sel ? vb : kb) + (size_t)(64 + r) * D_ + ch * 8;
            cp_async16(dst, src);
        }
        cp_commit();

        cp_wait<1>();
        __syncthreads();

        uint32_t qfr[2][4][4];
        #pragma unroll
        for (int mf = 0; mf < 2; mf++)
            #pragma unroll
            for (int kc = 0; kc < 4; kc++)
                ldsm_x4(qfr[mf][kc],
                    Qs_u + (uint32_t)((wid * 32 + mf * 16 + lr) * AT_STR + kc * 16 + 8 * lc) * 2);

        float mr[2][2] = {{-1e30f, -1e30f}, {-1e30f, -1e30f}};
        float lr_[2][2] = {{0.f, 0.f}, {0.f, 0.f}};
        float ofr[2][8][4];
        #pragma unroll
        for (int mf = 0; mf < 2; mf++)
            #pragma unroll
            for (int nf = 0; nf < 8; nf++)
                #pragma unroll
                for (int i = 0; i < 4; i++) ofr[mf][nf][i] = 0.f;

        int ntiles = q0 / 64 + 2;
        int rowtop = q0 + wid * 32 + 31;

        for (int it = 0; it < ntiles; it++) {
            if (it > 0) {
                cp_wait<1>();
                __syncthreads();
            }

            int itp = it + 2;
            if (itp < ntiles) {
                int j0p = itp * 64;
                uint32_t stp = (uint32_t)((itp % 3) * 64 * AT_STR) * 2;
                #pragma unroll
                for (int l = 0; l < 8; l++) {
                    int p = tid + l * 128;
                    int sel = p >> 9;
                    int pp = p & 511;
                    int r = pp >> 3, ch = pp & 7;
                    uint32_t dst = (sel ? Vs_u : Ks_u) + stp
                                 + (uint32_t)(r * AT_STR + ch * 8) * 2;
                    const __half* src = (sel ? vb : kb) + (size_t)(j0p + r) * D_ + ch * 8;
                    cp_async16(dst, src);
                }
            }
            cp_commit();

            int j0 = it * 64;
            int st = it % 3;
            int rowmax_rel = rowtop - j0;
            if (rowmax_rel >= 0) {
                uint32_t Kt_u = Ks_u + (uint32_t)(st * 64 * AT_STR) * 2;
                uint32_t Vt_u = Vs_u + (uint32_t)(st * 64 * AT_STR) * 2;

                float sfr[2][8][4];
                #pragma unroll
                for (int mf = 0; mf < 2; mf++)
                    #pragma unroll
                    for (int nf = 0; nf < 8; nf++)
                        #pragma unroll
                        for (int i = 0; i < 4; i++) sfr[mf][nf][i] = 0.f;

                #pragma unroll
                for (int kc = 0; kc < 4; kc++) {
                    int k0 = kc * 16 + 8 * lc;
                    #pragma unroll
                    for (int np = 0; np < 4; np++) {
                        if (np * 16 <= rowmax_rel) {
                            uint32_t bfr[4];
                            ldsm_x4(bfr, Kt_u + (uint32_t)((np * 16 + lr) * AT_STR + k0) * 2);
                            mma_f16(sfr[0][2*np+0], qfr[0][kc][0], qfr[0][kc][1], qfr[0][kc][2], qfr[0][kc][3], bfr[0], bfr[2]);
                            mma_f16(sfr[1][2*np+0], qfr[1][kc][0], qfr[1][kc][1], qfr[1][kc][2], qfr[1][kc][3], bfr[0], bfr[2]);
                            mma_f16(sfr[0][2*np+1], qfr[0][kc][0], qfr[0][kc][1], qfr[0][kc][2], qfr[0][kc][3], bfr[1], bfr[3]);
                            mma_f16(sfr[1][2*np+1], qfr[1][kc][0], qfr[1][kc][1], qfr[1][kc][2], qfr[1][kc][3], bfr[1], bfr[3]);
                        }
                    }
                }

                if (j0 + 64 > q0) {
                    #pragma unroll
                    for (int mf = 0; mf < 2; mf++) {
                        int gi = q0 + wid * 32 + mf * 16 + g;
                        #pragma unroll
                        for (int nf = 0; nf < 8; nf++) {
                            int gj = j0 + nf * 8 + 2 * c;
                            if (gj     > gi)     sfr[mf][nf][0] = -1e30f;
                            if (gj + 1 > gi)     sfr[mf][nf][1] = -1e30f;
                            if (gj     > gi + 8) sfr[mf][nf][2] = -1e30f;
                            if (gj + 1 > gi + 8) sfr[mf][nf][3] = -1e30f;
                        }
                    }
                }

                uint32_t ph0[2][8], ph1[2][8];
                #pragma unroll
                for (int mf = 0; mf < 2; mf++) {
                    float mx0 = -1e30f, mx1 = -1e30f;
                    #pragma unroll
                    for (int nf = 0; nf < 8; nf++) {
                        mx0 = fmaxf(mx0, fmaxf(sfr[mf][nf][0], sfr[mf][nf][1]));
                        mx1 = fmaxf(mx1, fmaxf(sfr[mf][nf][2], sfr[mf][nf][3]));
                    }
                    mx0 = fmaxf(mx0, __shfl_xor_sync(0xffffffffu, mx0, 1));
                    mx0 = fmaxf(mx0, __shfl_xor_sync(0xffffffffu, mx0, 2));
                    mx1 = fmaxf(mx1, __shfl_xor_sync(0xffffffffu, mx1, 1));
                    mx1 = fmaxf(mx1, __shfl_xor_sync(0xffffffffu, mx1, 2));

                    float mn0 = fmaxf(mr[mf][0], mx0);
                    float mn1 = fmaxf(mr[mf][1], mx1);
                    float al0 = exp2f(mr[mf][0] - mn0);
                    float al1 = exp2f(mr[mf][1] - mn1);
                    mr[mf][0] = mn0; mr[mf][1] = mn1;

                    float sum0 = 0.f, sum1 = 0.f;
                    #pragma unroll
                    for (int nf = 0; nf < 8; nf++) {
                        float p0 = exp2f(sfr[mf][nf][0] - mn0);
                        float p1 = exp2f(sfr[mf][nf][1] - mn0);
                        float p2 = exp2f(sfr[mf][nf][2] - mn1);
                        float p3 = exp2f(sfr[mf][nf][3] - mn1);
                        sum0 += p0 + p1;
                        sum1 += p2 + p3;
                        __half2 h01 = __floats2half2_rn(p0, p1);
                        __half2 h23 = __floats2half2_rn(p2, p3);
                        ph0[mf][nf] = *(uint32_t*)&h01;
                        ph1[mf][nf] = *(uint32_t*)&h23;
                    }
                    lr_[mf][0] = lr_[mf][0] * al0 + sum0;
                    lr_[mf][1] = lr_[mf][1] * al1 + sum1;

                    #pragma unroll
                    for (int nf = 0; nf < 8; nf++) {
                        ofr[mf][nf][0] *= al0; ofr[mf][nf][1] *= al0;
                        ofr[mf][nf][2] *= al1; ofr[mf][nf][3] *= al1;
                    }
                }

                #pragma unroll
                for (int kc = 0; kc < 4; kc++) {
                    if (kc * 16 <= rowmax_rel) {
                        #pragma unroll
                        for (int np = 0; np < 4; np++) {
                            uint32_t bfr[4];
                            ldsm_x4t(bfr, Vt_u +
                                (uint32_t)((kc * 16 + lr) * AT_STR + np * 16 + 8 * lc) * 2);
                            #pragma unroll
                            for (int mf = 0; mf < 2; mf++) {
                                uint32_t a0 = ph0[mf][2*kc],   a1 = ph1[mf][2*kc];
                                uint32_t a2 = ph0[mf][2*kc+1], a3 = ph1[mf][2*kc+1];
                                mma_f16(ofr[mf][2*np+0], a0, a1, a2, a3, bfr[0], bfr[1]);
                                mma_f16(ofr[mf][2*np+1], a0, a1, a2, a3, bfr[2], bfr[3]);
                            }
                        }
                    }
                }
            }
        }

        #pragma unroll
        for (int mf = 0; mf < 2; mf++) {
            float s0 = lr_[mf][0], s1 = lr_[mf][1];
            s0 += __shfl_xor_sync(0xffffffffu, s0, 1);
            s0 += __shfl_xor_sync(0xffffffffu, s0, 2);
            s1 += __shfl_xor_sync(0xffffffffu, s1, 1);
            s1 += __shfl_xor_sync(0xffffffffu, s1, 2);
            float inv0 = 1.f / s0, inv1 = 1.f / s1;
            int row0 = q0 + wid * 32 + mf * 16 + g;
            size_t base0 = (((size_t)b * S_ + row0) * H_ + h) * D_;
            size_t base1 = (((size_t)b * S_ + row0 + 8) * H_ + h) * D_;
            #pragma unroll
            for (int nf = 0; nf < 8; nf++) {
                int col = nf * 8 + 2 * c;
                __half2 r0 = __floats2half2_rn(ofr[mf][nf][0] * inv0, ofr[mf][nf][1] * inv0);
                __half2 r1 = __floats2half2_rn(ofr[mf][nf][2] * inv1, ofr[mf][nf][3] * inv1);
                *(__half2*)(o + base0 + col) = r0;
                *(__half2*)(o + base1 + col) = r1;
            }
        }
    }
}

// ---------------------------------------------------------------------------
extern "C" void kernel_launch(void* const* d_in, const int* in_sizes, int n_in,
                              void* d_out, int out_size)
{
    const float* x  = (const float*)d_in[0];
    const float* Wq = (const float*)d_in[1];
    const float* bq = (const float*)d_in[2];
    const float* Wk = (const float*)d_in[3];
    const float* bk = (const float*)d_in[4];
    const float* Wv = (const float*)d_in[5];
    const float* bv = (const float*)d_in[6];
    const float* Wp = (const float*)d_in[7];
    const float* bp = (const float*)d_in[8];
    float* out = (float*)d_out;

    __half *xp, *qkvp, *op, *wqkvt, *wpt;
    cudaGetSymbolAddress((void**)&xp, g_x);
    cudaGetSymbolAddress((void**)&qkvp, g_qkv);
    cudaGetSymbolAddress((void**)&op, g_o);
    cudaGetSymbolAddress((void**)&wqkvt, g_wqkvt);
    cudaGetSymbolAddress((void**)&wpt, g_wpt);

    cudaFuncSetAttribute(attn_kernel,
                         cudaFuncAttributeMaxDynamicSharedMemorySize, ATTN_SMEM);
    cudaFuncSetAttribute(gemm_mma<0>,
                         cudaFuncAttributeMaxDynamicSharedMemorySize, GEMM_SMEM);
    cudaFuncSetAttribute(gemm_mma<1>,
                         cudaFuncAttributeMaxDynamicSharedMemorySize, GEMM_SMEM);

    // Fused pre-pass (one launch)
    prep_kernel<<<8192, 256>>>(x, Wq, Wk, Wv, Wp, xp, wqkvt, wpt);

    // Fused QKV projection, N = 3072 (q pre-scaled by QSCALE)
    dim3 gg(T_ / 128, 3 * HD_ / 256);                // 64 x 12
    gemm_mma<0><<<gg, 512, GEMM_SMEM>>>(xp, wqkvt, bq, bk, bv, qkvp);

    // Attention: work-balanced q-tile pairs (bx, 15-bx)
    __half* qp = qkvp;
    __half* kp = qkvp + (size_t)T_ * HD_;
    __half* vp = qkvp + (size_t)2 * T_ * HD_;
    dim3 gattn(NQT / 2, B_ * H_);                    // 8 x 64
    attn_kernel<<<gattn, 128, ATTN_SMEM>>>(qp, kp, vp, op);

    // Output projection
    dim3 gp(T_ / 128, E_ / 256);                     // 64 x 4
    gemm_mma<1><<<gp, 512, GEMM_SMEM>>>(op, wpt, bp, bp, bp, out);
}

// round 17
// speedup vs baseline: 1.6441x; 1.6441x over previous
#include <cuda_runtime.h>
#include <cuda_fp16.h>
#include <cstdint>
#include <math.h>

#define B_  4
#define S_  2048
#define E_  1024
#define H_  16
#define D_  64
#define T_  (B_*S_)     // 8192 tokens
#define HD_ (H_*D_)     // 1024

// softmax scale folded into q at QKV epilogue: 1/sqrt(64) * log2(e)
#define QSCALE (0.125f * 1.4426950408889634f)

// ---------------------------------------------------------------------------
// Scratch (static device arrays; no runtime allocation)
// ---------------------------------------------------------------------------
__device__ __half g_x[(size_t)T_*E_];          // fp16 x [T,E]
__device__ __half g_qkv[(size_t)3*T_*HD_];     // q|k|v, each [B,H,S,D] (q pre-scaled)
__device__ __half g_o[(size_t)T_*HD_];         // ctx [B,S,H,D] == [T, HD]
__device__ __half g_wqkvt[(size_t)3*HD_*E_];   // K-major [n][e], q|k|v
__device__ __half g_wpt[(size_t)E_*HD_];       // K-major [n=e][c]

// ---------------------------------------------------------------------------
// PTX helpers (plain sm_103-target-safe: mma.sync + ldmatrix + cp.async)
// ---------------------------------------------------------------------------
__device__ __forceinline__ uint32_t smem_u32(const void* p) {
    return (uint32_t)__cvta_generic_to_shared(p);
}
__device__ __forceinline__ void cp_async16(uint32_t dst, const void* src) {
    asm volatile("cp.async.cg.shared.global [%0], [%1], 16;\n" :: "r"(dst), "l"(src));
}
__device__ __forceinline__ void cp_commit() {
    asm volatile("cp.async.commit_group;\n" ::: "memory");
}
template<int N> __device__ __forceinline__ void cp_wait() {
    asm volatile("cp.async.wait_group %0;\n" :: "n"(N) : "memory");
}
__device__ __forceinline__ void mma_f16(float* c,
    uint32_t a0, uint32_t a1, uint32_t a2, uint32_t a3,
    uint32_t b0, uint32_t b1)
{
    asm volatile(
        "mma.sync.aligned.m16n8k16.row.col.f32.f16.f16.f32 "
        "{%0,%1,%2,%3},{%4,%5,%6,%7},{%8,%9},{%0,%1,%2,%3};"
        : "+f"(c[0]), "+f"(c[1]), "+f"(c[2]), "+f"(c[3])
        : "r"(a0), "r"(a1), "r"(a2), "r"(a3), "r"(b0), "r"(b1));
}
__device__ __forceinline__ void ldsm_x4(uint32_t* r, uint32_t a) {
    asm volatile("ldmatrix.sync.aligned.m8n8.x4.shared.b16 {%0,%1,%2,%3}, [%4];"
        : "=r"(r[0]), "=r"(r[1]), "=r"(r[2]), "=r"(r[3]) : "r"(a));
}
__device__ __forceinline__ void ldsm_x4t(uint32_t* r, uint32_t a) {
    asm volatile("ldmatrix.sync.aligned.m8n8.x4.trans.shared.b16 {%0,%1,%2,%3}, [%4];"
        : "=r"(r[0]), "=r"(r[1]), "=r"(r[2]), "=r"(r[3]) : "r"(a));
}

// ---------------------------------------------------------------------------
// Fused pre-pass: one launch, three sections by blockIdx.x
// ---------------------------------------------------------------------------
__global__ __launch_bounds__(256) void prep_kernel(
    const float* __restrict__ x,
    const float* __restrict__ Wq,
    const float* __restrict__ Wk,
    const float* __restrict__ Wv,
    const float* __restrict__ Wp,
    __half* __restrict__ xd,
    __half* __restrict__ wqkvt,
    __half* __restrict__ wpt)
{
    __shared__ float tile[32][33];
    int bid = blockIdx.x;
    int tid = threadIdx.x;

    if (bid < 4096) {
        int i = (bid * 256 + tid) * 8;
        float4 v0 = *(const float4*)(x + i);
        float4 v1 = *(const float4*)(x + i + 4);
        __half2 h0 = __floats2half2_rn(v0.x, v0.y);
        __half2 h1 = __floats2half2_rn(v0.z, v0.w);
        __half2 h2 = __floats2half2_rn(v1.x, v1.y);
        __half2 h3 = __floats2half2_rn(v1.z, v1.w);
        uint4 st;
        st.x = *(uint32_t*)&h0; st.y = *(uint32_t*)&h1;
        st.z = *(uint32_t*)&h2; st.w = *(uint32_t*)&h3;
        *(uint4*)(xd + i) = st;
        return;
    }

    int tx = tid & 31, ty = tid >> 5;

    if (bid < 7168) {
        int idx = bid - 4096;
        int z = idx >> 6;
        int r0 = ((idx >> 1) & 31) * 32;
        int c0 = (idx & 1) * 32;
        const float* W = (z < 16) ? Wq : (z < 32) ? Wk : Wv;
        const float* s = W + (size_t)(z & 15) * E_ * D_;
        __half* d = wqkvt + (size_t)z * D_ * E_;
        #pragma unroll
        for (int i = ty; i < 32; i += 8)
            tile[i][tx] = s[(size_t)(r0 + i) * D_ + c0 + tx];
        __syncthreads();
        #pragma unroll
        for (int i = ty; i < 32; i += 8)
            d[(size_t)(c0 + i) * E_ + r0 + tx] = __float2half(tile[tx][i]);
        return;
    }

    {
        int idx = bid - 7168;
        int c0 = (idx & 31) * 32;
        int r0 = (idx >> 5) * 32;
        #pragma unroll
        for (int i = ty; i < 32; i += 8)
            tile[i][tx] = Wp[(size_t)(r0 + i) * E_ + c0 + tx];
        __syncthreads();
        #pragma unroll
        for (int i = ty; i < 32; i += 8)
            wpt[(size_t)(c0 + i) * HD_ + r0 + tx] = __float2half(tile[tx][i]);
    }
}

// ---------------------------------------------------------------------------
// fp16 mma.sync GEMM (proven optimum): CTA 128x128, BK=64, 3 stages,
// 256 threads, 8 warps (4m x 2n), warp tile 32x64, 2 CTAs/SM.
// MODE 0: fused QKV -> g_qkv; q section scaled by QSCALE.  MODE 1: [T,E] fp32.
// ---------------------------------------------------------------------------
#define GEMM_BK     64
#define GEMM_STAGES 3
#define GEMM_KT     (E_ / GEMM_BK)           // 16
#define GEMM_STR    72
#define GEMM_TILEH  (128 * GEMM_STR)
#define GEMM_STAGEH (2 * GEMM_TILEH)
#define GEMM_SMEM   (GEMM_STAGES * GEMM_STAGEH * 2)    // 110592 B

__device__ __forceinline__ void gemm_load_stage(
    const __half* __restrict__ Ag, const __half* __restrict__ Bg,
    uint32_t abase, uint32_t bbase, int tid)
{
    #pragma unroll
    for (int j = 0; j < 4; j++) {
        int p = tid + j * 256;
        int r = p >> 3;
        int ch = p & 7;
        uint32_t off = (uint32_t)(r * (GEMM_STR * 2) + ch * 16);
        cp_async16(abase + off, Ag + (size_t)r * E_ + ch * 8);
        cp_async16(bbase + off, Bg + (size_t)r * E_ + ch * 8);
    }
}

template<int MODE>
__global__ __launch_bounds__(256, 2) void gemm_mma(
    const __half* __restrict__ A,
    const __half* __restrict__ Bw,
    const float* __restrict__ b0p,
    const float* __restrict__ b1p,
    const float* __restrict__ b2p,
    void* __restrict__ outp)
{
    extern __shared__ __align__(16) __half smem[];
    uint32_t sb = smem_u32(smem);

    int tid = threadIdx.x;
    int wid = tid >> 5, lane = tid & 31;
    int g = lane >> 2, c = lane & 3;
    int lr = lane & 15, lc = lane >> 4;
    int wm = wid & 3, wn = wid >> 2;
    int m0 = blockIdx.x * 128;
    int n0 = blockIdx.y * 128;

    const __half* Abase = A + (size_t)m0 * E_;
    const __half* Bbase = Bw + (size_t)n0 * E_;

    float cfr[2][8][4];
    #pragma unroll
    for (int mf = 0; mf < 2; mf++)
        #pragma unroll
        for (int nf = 0; nf < 8; nf++)
            #pragma unroll
            for (int i = 0; i < 4; i++) cfr[mf][nf][i] = 0.f;

    #pragma unroll
    for (int s = 0; s < GEMM_STAGES - 1; s++) {
        gemm_load_stage(Abase + s * GEMM_BK, Bbase + s * GEMM_BK,
                        sb + s * GEMM_STAGEH * 2,
                        sb + (s * GEMM_STAGEH + GEMM_TILEH) * 2, tid);
        cp_commit();
    }

    for (int kt = 0; kt < GEMM_KT; kt++) {
        cp_wait<GEMM_STAGES - 2>();
        __syncthreads();

        int ktn = kt + GEMM_STAGES - 1;
        if (ktn < GEMM_KT) {
            int sn = ktn % GEMM_STAGES;
            gemm_load_stage(Abase + ktn * GEMM_BK, Bbase + ktn * GEMM_BK,
                            sb + sn * GEMM_STAGEH * 2,
                            sb + (sn * GEMM_STAGEH + GEMM_TILEH) * 2, tid);
        }
        cp_commit();

        int s = kt % GEMM_STAGES;
        uint32_t As_u = sb + s * GEMM_STAGEH * 2;
        uint32_t Bs_u = As_u + GEMM_TILEH * 2;

        #pragma unroll
        for (int kc = 0; kc < 4; kc++) {
            int k0 = kc * 16 + 8 * lc;
            uint32_t afr[2][4];
            #pragma unroll
            for (int mf = 0; mf < 2; mf++)
                ldsm_x4(afr[mf],
                    As_u + (uint32_t)((wm * 32 + mf * 16 + lr) * GEMM_STR + k0) * 2);
            #pragma unroll
            for (int np = 0; np < 4; np++) {
                uint32_t bfr[4];
                ldsm_x4(bfr,
                    Bs_u + (uint32_t)((wn * 64 + np * 16 + lr) * GEMM_STR + k0) * 2);
                mma_f16(cfr[0][2*np+0], afr[0][0], afr[0][1], afr[0][2], afr[0][3], bfr[0], bfr[2]);
                mma_f16(cfr[1][2*np+0], afr[1][0], afr[1][1], afr[1][2], afr[1][3], bfr[0], bfr[2]);
                mma_f16(cfr[0][2*np+1], afr[0][0], afr[0][1], afr[0][2], afr[0][3], bfr[1], bfr[3]);
                mma_f16(cfr[1][2*np+1], afr[1][0], afr[1][1], afr[1][2], afr[1][3], bfr[1], bfr[3]);
            }
        }
    }

    #pragma unroll
    for (int mf = 0; mf < 2; mf++) {
        #pragma unroll
        for (int half_ = 0; half_ < 2; half_++) {
            int row = wm * 32 + mf * 16 + g + half_ * 8;
            int t = m0 + row;
            #pragma unroll
            for (int nf = 0; nf < 8; nf++) {
                int col = n0 + wn * 64 + nf * 8 + 2 * c;
                const float* bp_ = (col < 1024) ? b0p : (col < 2048) ? b1p : b2p;
                int cb = col & 1023;
                float vx = cfr[mf][nf][2 * half_ + 0] + bp_[cb];
                float vy = cfr[mf][nf][2 * half_ + 1] + bp_[cb + 1];
                if (MODE == 0) {
                    if (col < 1024) { vx *= QSCALE; vy *= QSCALE; }
                    __half* ob = (__half*)outp + (size_t)(col >> 10) * ((size_t)T_ * HD_);
                    int b = t >> 11, s_ = t & 2047;
                    int h = cb >> 6, d0 = cb & 63;
                    __half2 hv = __floats2half2_rn(vx, vy);
                    *(__half2*)(ob + (((size_t)(b * H_ + h)) * S_ + s_) * D_ + d0) = hv;
                } else {
                    float2 v; v.x = vx; v.y = vy;
                    *(float2*)((float*)outp + (size_t)t * E_ + col) = v;
                }
            }
        }
    }
}

// ---------------------------------------------------------------------------
// Flash attention (proven optimum): 128 threads / 4 warps, m32 x n64 warp
// tiles, BQ=128, balanced q-tile pairs, 2-stage KV double buffer.
// Q fragments hoisted; lane-local l sums reduced at finalize.
// ---------------------------------------------------------------------------
#define AT_STR 72          // halfs per smem row (64 + 8 pad)
#define ATTN_SMEM ((128 + 2*64 + 2*64) * AT_STR * 2)   // 55296 B
#define NQT (S_ / 128)     // 16 q-tiles

__global__ __launch_bounds__(128, 2) void attn_kernel(
    const __half* __restrict__ q,
    const __half* __restrict__ k,
    const __half* __restrict__ v,
    __half* __restrict__ o)
{
    extern __shared__ __align__(16) __half smh[];
    __half* Qs = smh;                        // [128][72]
    __half* Ks = Qs + 128 * AT_STR;          // [2][64][72]
    __half* Vs = Ks + 2 * 64 * AT_STR;       // [2][64][72]

    uint32_t Qs_u = smem_u32(Qs);
    uint32_t Ks_u = smem_u32(Ks);
    uint32_t Vs_u = smem_u32(Vs);

    int tid = threadIdx.x;
    int lane = tid & 31, wid = tid >> 5;     // 4 warps, warp = 32 q-rows
    int g = lane >> 2, c = lane & 3;
    int lr = lane & 15, lc = lane >> 4;
    int bx = blockIdx.x;                     // 0..7
    int bh = blockIdx.y;

    const __half* qb = q + (size_t)bh * S_ * D_;
    const __half* kb = k + (size_t)bh * S_ * D_;
    const __half* vb = v + (size_t)bh * S_ * D_;
    int b = bh >> 4, h = bh & 15;

    #pragma unroll 1
    for (int pass = 0; pass < 2; pass++) {
        int qt = pass ? bx : (NQT - 1 - bx);     // long tile first
        int q0 = qt * 128;

        // Fence pass-0 laggards before overwriting Qs / stage buffers
        __syncthreads();

        #pragma unroll
        for (int it = 0; it < 8; it++) {
            int p = tid + it * 128;
            int r = p >> 3, ch = p & 7;
            cp_async16(Qs_u + (uint32_t)(r * AT_STR + ch * 8) * 2,
                       qb + (size_t)(q0 + r) * D_ + ch * 8);
        }
        #pragma unroll
        for (int it = 0; it < 8; it++) {
            int p = tid + it * 128;
            int sel = p >> 9;
            int pp = p & 511;
            int r = pp >> 3, ch = pp & 7;
            uint32_t dst = (sel ? Vs_u : Ks_u) + (uint32_t)(r * AT_STR + ch * 8) * 2;
            const __half* src = (sel ? vb : kb) + (size_t)r * D_ + ch * 8;
            cp_async16(dst, src);
        }
        cp_commit();
        cp_wait<0>();
        __syncthreads();

        // Hoist Q fragments (loop-invariant within pass)
        uint32_t qfr[2][4][4];
        #pragma unroll
        for (int mf = 0; mf < 2; mf++)
            #pragma unroll
            for (int kc = 0; kc < 4; kc++)
                ldsm_x4(qfr[mf][kc],
                    Qs_u + (uint32_t)((wid * 32 + mf * 16 + lr) * AT_STR + kc * 16 + 8 * lc) * 2);

        float mr[2][2] = {{-1e30f, -1e30f}, {-1e30f, -1e30f}};
        float lr_[2][2] = {{0.f, 0.f}, {0.f, 0.f}};
        float ofr[2][8][4];
        #pragma unroll
        for (int mf = 0; mf < 2; mf++)
            #pragma unroll
            for (int nf = 0; nf < 8; nf++)
                #pragma unroll
                for (int i = 0; i < 4; i++) ofr[mf][nf][i] = 0.f;

        int ntiles = q0 / 64 + 2;
        int rowtop = q0 + wid * 32 + 31;

        for (int it = 0; it < ntiles; it++) {
            int j0 = it * 64;
            int st = it & 1;

            if (it + 1 < ntiles) {
                int j0n = j0 + 64;
                uint32_t kd = Ks_u + (uint32_t)((st ^ 1) * 64 * AT_STR) * 2;
                uint32_t vd = Vs_u + (uint32_t)((st ^ 1) * 64 * AT_STR) * 2;
                #pragma unroll
                for (int l = 0; l < 8; l++) {
                    int p = tid + l * 128;
                    int sel = p >> 9;
                    int pp = p & 511;
                    int r = pp >> 3, ch = pp & 7;
                    uint32_t dst = (sel ? vd : kd) + (uint32_t)(r * AT_STR + ch * 8) * 2;
                    const __half* src = (sel ? vb : kb) + (size_t)(j0n + r) * D_ + ch * 8;
                    cp_async16(dst, src);
                }
            }
            cp_commit();
            cp_wait<1>();
            __syncthreads();

            int rowmax_rel = rowtop - j0;
            if (rowmax_rel >= 0) {
                uint32_t Kt_u = Ks_u + (uint32_t)(st * 64 * AT_STR) * 2;
                uint32_t Vt_u = Vs_u + (uint32_t)(st * 64 * AT_STR) * 2;

                float sfr[2][8][4];
                #pragma unroll
                for (int mf = 0; mf < 2; mf++)
                    #pragma unroll
                    for (int nf = 0; nf < 8; nf++)
                        #pragma unroll
                        for (int i = 0; i < 4; i++) sfr[mf][nf][i] = 0.f;

                #pragma unroll
                for (int kc = 0; kc < 4; kc++) {
                    int k0 = kc * 16 + 8 * lc;
                    #pragma unroll
                    for (int np = 0; np < 4; np++) {
                        if (np * 16 <= rowmax_rel) {
                            uint32_t bfr[4];
                            ldsm_x4(bfr, Kt_u + (uint32_t)((np * 16 + lr) * AT_STR + k0) * 2);
                            mma_f16(sfr[0][2*np+0], qfr[0][kc][0], qfr[0][kc][1], qfr[0][kc][2], qfr[0][kc][3], bfr[0], bfr[2]);
                            mma_f16(sfr[1][2*np+0], qfr[1][kc][0], qfr[1][kc][1], qfr[1][kc][2], qfr[1][kc][3], bfr[0], bfr[2]);
                            mma_f16(sfr[0][2*np+1], qfr[0][kc][0], qfr[0][kc][1], qfr[0][kc][2], qfr[0][kc][3], bfr[1], bfr[3]);
                            mma_f16(sfr[1][2*np+1], qfr[1][kc][0], qfr[1][kc][1], qfr[1][kc][2], qfr[1][kc][3], bfr[1], bfr[3]);
                        }
                    }
                }

                if (j0 + 64 > q0) {
                    #pragma unroll
                    for (int mf = 0; mf < 2; mf++) {
                        int gi = q0 + wid * 32 + mf * 16 + g;
                        #pragma unroll
                        for (int nf = 0; nf < 8; nf++) {
                            int gj = j0 + nf * 8 + 2 * c;
                            if (gj     > gi)     sfr[mf][nf][0] = -1e30f;
                            if (gj + 1 > gi)     sfr[mf][nf][1] = -1e30f;
                            if (gj     > gi + 8) sfr[mf][nf][2] = -1e30f;
                            if (gj + 1 > gi + 8) sfr[mf][nf][3] = -1e30f;
                        }
                    }
                }

                uint32_t ph0[2][8], ph1[2][8];
                #pragma unroll
                for (int mf = 0; mf < 2; mf++) {
                    float mx0 = -1e30f, mx1 = -1e30f;
                    #pragma unroll
                    for (int nf = 0; nf < 8; nf++) {
                        mx0 = fmaxf(mx0, fmaxf(sfr[mf][nf][0], sfr[mf][nf][1]));
                        mx1 = fmaxf(mx1, fmaxf(sfr[mf][nf][2], sfr[mf][nf][3]));
                    }
                    mx0 = fmaxf(mx0, __shfl_xor_sync(0xffffffffu, mx0, 1));
                    mx0 = fmaxf(mx0, __shfl_xor_sync(0xffffffffu, mx0, 2));
                    mx1 = fmaxf(mx1, __shfl_xor_sync(0xffffffffu, mx1, 1));
                    mx1 = fmaxf(mx1, __shfl_xor_sync(0xffffffffu, mx1, 2));

                    float mn0 = fmaxf(mr[mf][0], mx0);
                    float mn1 = fmaxf(mr[mf][1], mx1);
                    float al0 = exp2f(mr[mf][0] - mn0);
                    float al1 = exp2f(mr[mf][1] - mn1);
                    mr[mf][0] = mn0; mr[mf][1] = mn1;

                    float sum0 = 0.f, sum1 = 0.f;
                    #pragma unroll
                    for (int nf = 0; nf < 8; nf++) {
                        float p0 = exp2f(sfr[mf][nf][0] - mn0);
                        float p1 = exp2f(sfr[mf][nf][1] - mn0);
                        float p2 = exp2f(sfr[mf][nf][2] - mn1);
                        float p3 = exp2f(sfr[mf][nf][3] - mn1);
                        sum0 += p0 + p1;
                        sum1 += p2 + p3;
                        __half2 h01 = __floats2half2_rn(p0, p1);
                        __half2 h23 = __floats2half2_rn(p2, p3);
                        ph0[mf][nf] = *(uint32_t*)&h01;
                        ph1[mf][nf] = *(uint32_t*)&h23;
                    }
                    lr_[mf][0] = lr_[mf][0] * al0 + sum0;
                    lr_[mf][1] = lr_[mf][1] * al1 + sum1;

                    #pragma unroll
                    for (int nf = 0; nf < 8; nf++) {
                        ofr[mf][nf][0] *= al0; ofr[mf][nf][1] *= al0;
                        ofr[mf][nf][2] *= al1; ofr[mf][nf][3] *= al1;
                    }
                }

                #pragma unroll
                for (int kc = 0; kc < 4; kc++) {
                    if (kc * 16 <= rowmax_rel) {
                        #pragma unroll
                        for (int np = 0; np < 4; np++) {
                            uint32_t bfr[4];
                            ldsm_x4t(bfr, Vt_u +
                                (uint32_t)((kc * 16 + lr) * AT_STR + np * 16 + 8 * lc) * 2);
                            #pragma unroll
                            for (int mf = 0; mf < 2; mf++) {
                                uint32_t a0 = ph0[mf][2*kc],   a1 = ph1[mf][2*kc];
                                uint32_t a2 = ph0[mf][2*kc+1], a3 = ph1[mf][2*kc+1];
                                mma_f16(ofr[mf][2*np+0], a0, a1, a2, a3, bfr[0], bfr[1]);
                                mma_f16(ofr[mf][2*np+1], a0, a1, a2, a3, bfr[2], bfr[3]);
                            }
                        }
                    }
                }
            }
            __syncthreads();
        }

        // ---- finalize: quad-reduce l, /l, write ctx [B,S,H,D] half ----
        #pragma unroll
        for (int mf = 0; mf < 2; mf++) {
            float s0 = lr_[mf][0], s1 = lr_[mf][1];
            s0 += __shfl_xor_sync(0xffffffffu, s0, 1);
            s0 += __shfl_xor_sync(0xffffffffu, s0, 2);
            s1 += __shfl_xor_sync(0xffffffffu, s1, 1);
            s1 += __shfl_xor_sync(0xffffffffu, s1, 2);
            float inv0 = 1.f / s0, inv1 = 1.f / s1;
            int row0 = q0 + wid * 32 + mf * 16 + g;
            size_t base0 = (((size_t)b * S_ + row0) * H_ + h) * D_;
            size_t base1 = (((size_t)b * S_ + row0 + 8) * H_ + h) * D_;
            #pragma unroll
            for (int nf = 0; nf < 8; nf++) {
                int col = nf * 8 + 2 * c;
                __half2 r0 = __floats2half2_rn(ofr[mf][nf][0] * inv0, ofr[mf][nf][1] * inv0);
                __half2 r1 = __floats2half2_rn(ofr[mf][nf][2] * inv1, ofr[mf][nf][3] * inv1);
                *(__half2*)(o + base0 + col) = r0;
                *(__half2*)(o + base1 + col) = r1;
            }
        }
    }
}

// ---------------------------------------------------------------------------
extern "C" void kernel_launch(void* const* d_in, const int* in_sizes, int n_in,
                              void* d_out, int out_size)
{
    const float* x  = (const float*)d_in[0];
    const float* Wq = (const float*)d_in[1];
    const float* bq = (const float*)d_in[2];
    const float* Wk = (const float*)d_in[3];
    const float* bk = (const float*)d_in[4];
    const float* Wv = (const float*)d_in[5];
    const float* bv = (const float*)d_in[6];
    const float* Wp = (const float*)d_in[7];
    const float* bp = (const float*)d_in[8];
    float* out = (float*)d_out;

    __half *xp, *qkvp, *op, *wqkvt, *wpt;
    cudaGetSymbolAddress((void**)&xp, g_x);
    cudaGetSymbolAddress((void**)&qkvp, g_qkv);
    cudaGetSymbolAddress((void**)&op, g_o);
    cudaGetSymbolAddress((void**)&wqkvt, g_wqkvt);
    cudaGetSymbolAddress((void**)&wpt, g_wpt);

    cudaFuncSetAttribute(attn_kernel,
                         cudaFuncAttributeMaxDynamicSharedMemorySize, ATTN_SMEM);
    cudaFuncSetAttribute(gemm_mma<0>,
                         cudaFuncAttributeMaxDynamicSharedMemorySize, GEMM_SMEM);
    cudaFuncSetAttribute(gemm_mma<1>,
                         cudaFuncAttributeMaxDynamicSharedMemorySize, GEMM_SMEM);

    // Fused pre-pass (one launch)
    prep_kernel<<<8192, 256>>>(x, Wq, Wk, Wv, Wp, xp, wqkvt, wpt);

    // Fused QKV projection, N = 3072 (q pre-scaled by QSCALE)
    dim3 gg(T_ / 128, 3 * HD_ / 128);                // 64 x 24
    gemm_mma<0><<<gg, 256, GEMM_SMEM>>>(xp, wqkvt, bq, bk, bv, qkvp);

    // Attention: work-balanced q-tile pairs (bx, 15-bx)
    __half* qp = qkvp;
    __half* kp = qkvp + (size_t)T_ * HD_;
    __half* vp = qkvp + (size_t)2 * T_ * HD_;
    dim3 gattn(NQT / 2, B_ * H_);                    // 8 x 64
    attn_kernel<<<gattn, 128, ATTN_SMEM>>>(qp, kp, vp, op);

    // Output projection
    dim3 gp(T_ / 128, E_ / 128);                     // 64 x 8
    gemm_mma<1><<<gp, 256, GEMM_SMEM>>>(op, wpt, bp, bp, bp, out);
}